// round 2
// baseline (speedup 1.0000x reference)
#include <cuda_runtime.h>

#define NB 32
#define NC 64
#define NS 64
#define NE 6   // distinct experts (PERM folds 8 gates onto 6)

// Scratch (device globals)
__device__ float g_c[4 * 16 * 64 * 32];            // [band][xy][i(chan)][b]
__device__ float g_Wt[4 * NE * 16 * 64 * 64];      // [band][e][xy][i][o]  (6.3MB)
__device__ float g_P[4 * NE * 32 * 16 * 64];       // [band][e][b][xy*64+o] (3MB)
__device__ float g_z[NB * NC * 64];                // [b][c][8*8] correction, pre-scaled 1/8
__device__ float g_Wsum[NB];

// ---------------------------------------------------------------------------
// kA: 8x8 block sums of x -> ll3, one Haar level -> 4 coefficient bands,
// written in [band][xy][chan][b] layout. One block per (b,c), 64 threads.
// ---------------------------------------------------------------------------
__global__ void kA(const float* __restrict__ x) {
    int bc = blockIdx.x;              // 0..2047   b = bc>>6, chan = bc&63
    int t = threadIdx.x;              // 0..63
    int i = t >> 3, j = t & 7;
    const float* xp = x + (size_t)bc * NS * NS + (size_t)i * 8 * NS + j * 8;
    float s = 0.f;
#pragma unroll
    for (int r = 0; r < 8; r++) {
        float4 a = *(const float4*)(xp + r * NS);
        float4 b = *(const float4*)(xp + r * NS + 4);
        s += a.x + a.y + a.z + a.w + b.x + b.y + b.z + b.w;
    }
    __shared__ float ll3[64];
    ll3[t] = s * 0.125f;              // 8x8 block sum / 8 == ll3
    __syncthreads();
    if (t < 16) {
        int xy = t;
        int xx = xy >> 2, yy = xy & 3;
        float a = ll3[(2 * xx) * 8 + 2 * yy];
        float b = ll3[(2 * xx) * 8 + 2 * yy + 1];
        float c = ll3[(2 * xx + 1) * 8 + 2 * yy];
        float d = ll3[(2 * xx + 1) * 8 + 2 * yy + 1];
        int bb = bc >> 6, ch = bc & 63;
        float v[4];
        v[0] = (a + b + c + d) * 0.5f; // ll
        v[1] = (a + b - c - d) * 0.5f; // lh
        v[2] = (a - b + c - d) * 0.5f; // hl
        v[3] = (a - b - c + d) * 0.5f; // hh
#pragma unroll
        for (int band = 0; band < 4; band++)
            g_c[((band * 16 + xy) * 64 + ch) * 32 + bb] = v[band];
    }
}

// ---------------------------------------------------------------------------
// kT: transpose weights into [band][e][xy][i][o]. 24 blocks, 256 threads.
// Each thread handles 16 (i,o) rows: reads 16 consecutive floats (4x float4),
// scatters one per xy (coalesced across threads for fixed xy).
// ---------------------------------------------------------------------------
__global__ void kT(const float* __restrict__ WL, const float* __restrict__ WH) {
    int be = blockIdx.x;              // 0..23: band*6+e
    int band = be / NE, e = be % NE;
    float* dst = g_Wt + (size_t)be * 16 * 4096;
    const float* src;
    if (band == 0) src = WL + (size_t)e * 65536;
    else           src = WH + (size_t)(e * 3 + (band - 1)) * 65536;
#pragma unroll
    for (int r = 0; r < 16; r++) {
        int io = threadIdx.x + 256 * r;      // 0..4095
        const float* sp = src + (size_t)io * 16;
        float4 q0 = *(const float4*)(sp);
        float4 q1 = *(const float4*)(sp + 4);
        float4 q2 = *(const float4*)(sp + 8);
        float4 q3 = *(const float4*)(sp + 12);
        float v[16] = {q0.x,q0.y,q0.z,q0.w, q1.x,q1.y,q1.z,q1.w,
                       q2.x,q2.y,q2.z,q2.w, q3.x,q3.y,q3.z,q3.w};
#pragma unroll
        for (int xy = 0; xy < 16; xy++)
            dst[(size_t)xy * 4096 + io] = v[xy];
    }
}

// ---------------------------------------------------------------------------
// kB1: per (band,e,xy): P[b,o] = sum_i c[b,i] * W[i,o].
// 384 blocks x 64 threads; each thread computes a 4b x 8o register tile
// straight from global (everything is L2-resident). No smem.
// ---------------------------------------------------------------------------
__global__ void kB1() {
    int blk = blockIdx.x;             // 0..383
    int xy = blk & 15;
    int e  = (blk >> 4) % NE;
    int band = blk / (16 * NE);
    int t = threadIdx.x;              // 0..63
    int b0 = (t >> 3) * 4;            // 8 b-groups
    int o0 = (t & 7) * 8;             // 8 o-groups

    const float* wp = g_Wt + ((size_t)(band * NE + e) * 16 + xy) * 4096 + o0;
    const float* cp = g_c + ((size_t)(band * 16 + xy) * 64) * 32 + b0;

    float acc[4][8];
#pragma unroll
    for (int bb = 0; bb < 4; bb++)
#pragma unroll
        for (int o = 0; o < 8; o++) acc[bb][o] = 0.f;

#pragma unroll 8
    for (int i = 0; i < 64; i++) {
        float4 c4 = *(const float4*)(cp + i * 32);
        float4 w0 = *(const float4*)(wp + (size_t)i * 64);
        float4 w1 = *(const float4*)(wp + (size_t)i * 64 + 4);
        float cb[4] = {c4.x, c4.y, c4.z, c4.w};
        float wo[8] = {w0.x, w0.y, w0.z, w0.w, w1.x, w1.y, w1.z, w1.w};
#pragma unroll
        for (int bb = 0; bb < 4; bb++)
#pragma unroll
            for (int o = 0; o < 8; o++) acc[bb][o] += cb[bb] * wo[o];
    }

    float* Pp = g_P + ((size_t)(band * NE + e) * 32) * 1024 + xy * 64 + o0;
#pragma unroll
    for (int bb = 0; bb < 4; bb++) {
        float* q = Pp + (size_t)(b0 + bb) * 1024;
        *(float4*)(q)     = make_float4(acc[bb][0], acc[bb][1], acc[bb][2], acc[bb][3]);
        *(float4*)(q + 4) = make_float4(acc[bb][4], acc[bb][5], acc[bb][6], acc[bb][7]);
    }
}

// ---------------------------------------------------------------------------
// kB2: gate-weighted combine over experts, subtract identity, 4x4->8x8 IDWT,
// pre-scale 1/8. 32 blocks (b), 1024 threads (xy*64+o). All reads coalesced.
// ---------------------------------------------------------------------------
__global__ void kB2(const float* __restrict__ lam) {
    int b = blockIdx.x;
    __shared__ float w[6];
    __shared__ float Wt;
    if (threadIdx.x == 0) {
        float l[8];
#pragma unroll
        for (int g = 0; g < 8; g++) l[g] = lam[b * 8 + g];
        w[0] = l[0]; w[1] = l[1]; w[2] = l[2]; w[3] = l[3];
        w[4] = l[4] + l[6]; w[5] = l[5] + l[7];
        float s = l[0] + l[1] + l[2] + l[3] + l[4] + l[5] + l[6] + l[7];
        Wt = s;
        g_Wsum[b] = s;
    }
    __syncthreads();

    int t = threadIdx.x;
    int xy = t >> 6, o = t & 63;
    float Sv[4];
#pragma unroll
    for (int band = 0; band < 4; band++) {
        float s = 0.f;
#pragma unroll
        for (int e = 0; e < NE; e++)
            s += w[e] * g_P[((size_t)(band * NE + e) * 32 + b) * 1024 + t];
        float orig = g_c[((size_t)(band * 16 + xy) * 64 + o) * 32 + b];
        Sv[band] = s - Wt * orig;
    }
    float x00 = (Sv[0] + Sv[1] + Sv[2] + Sv[3]) * 0.0625f;
    float x01 = (Sv[0] + Sv[1] - Sv[2] - Sv[3]) * 0.0625f;
    float x10 = (Sv[0] - Sv[1] + Sv[2] - Sv[3]) * 0.0625f;
    float x11 = (Sv[0] - Sv[1] - Sv[2] + Sv[3]) * 0.0625f;
    int xx = xy >> 2, yy = xy & 3;
    float* zp = g_z + (size_t)(b * 64 + o) * 64;
    zp[(2 * xx) * 8 + 2 * yy]         = x00;
    zp[(2 * xx) * 8 + 2 * yy + 1]     = x01;
    zp[(2 * xx + 1) * 8 + 2 * yy]     = x10;
    zp[(2 * xx + 1) * 8 + 2 * yy + 1] = x11;
}

// ---------------------------------------------------------------------------
// kC: out = Wsum[b] * x + z[b,c,h/8,w/8].  8 consecutive floats per thread
// (2x float4) -> exactly one z cell per thread, doubled MLP.
// ---------------------------------------------------------------------------
__global__ void kC(const float* __restrict__ x, float* __restrict__ out) {
    int tid = blockIdx.x * blockDim.x + threadIdx.x;  // 0..1048575
    int e0 = tid << 3;
    int b = e0 >> 18;
    int c = (e0 >> 12) & 63;
    int h = (e0 >> 6) & 63;
    int w0 = e0 & 63;                 // multiple of 8
    float W = g_Wsum[b];
    float zv = g_z[(size_t)((b << 6) + c) * 64 + (h >> 3) * 8 + (w0 >> 3)];
    float4 xa = *(const float4*)(x + e0);
    float4 xb = *(const float4*)(x + e0 + 4);
    float4 oa, ob;
    oa.x = fmaf(W, xa.x, zv); oa.y = fmaf(W, xa.y, zv);
    oa.z = fmaf(W, xa.z, zv); oa.w = fmaf(W, xa.w, zv);
    ob.x = fmaf(W, xb.x, zv); ob.y = fmaf(W, xb.y, zv);
    ob.z = fmaf(W, xb.z, zv); ob.w = fmaf(W, xb.w, zv);
    *(float4*)(out + e0)     = oa;
    *(float4*)(out + e0 + 4) = ob;
}

// ---------------------------------------------------------------------------
extern "C" void kernel_launch(void* const* d_in, const int* in_sizes, int n_in,
                              void* d_out, int out_size) {
    const float* x   = (const float*)d_in[0];  // [32,64,64,64]
    const float* lam = (const float*)d_in[1];  // [32,1,8,1]
    const float* WL  = (const float*)d_in[2];  // [8,64,64,4,4]
    const float* WH  = (const float*)d_in[3];  // [8,3,64,64,4,4]
    float* out = (float*)d_out;

    kT<<<4 * NE, 256>>>(WL, WH);
    kA<<<NB * NC, 64>>>(x);
    kB1<<<4 * NE * 16, 64>>>();
    kB2<<<NB, 1024>>>(lam);
    kC<<<(NB * NC * NS * NS / 8 + 255) / 256, 256>>>(x, out);
    (void)in_sizes; (void)n_in; (void)out_size;
}

// round 3
// speedup vs baseline: 1.2385x; 1.2385x over previous
#include <cuda_runtime.h>

#define NB 32
#define NC 64
#define NS 64
#define NE 6   // distinct experts (PERM folds 8 gates onto 6)

// Scratch (device globals)
__device__ float g_c [4 * 16 * 64 * 32];           // [band][xy][i(chan)][b]   (for kB1)
__device__ float g_c2[4 * 32 * 16 * 64];           // [band][b][xy][chan]      (for kB2, coalesced)
__device__ float g_Wt[4 * NE * 16 * 64 * 64];      // [band][e][xy][i][o]  (6.3MB)
__device__ float g_P[4 * NE * 32 * 16 * 64];       // [band][e][b][xy*64+o] (3MB)
__device__ float g_z[NB * NC * 64];                // [b][c][8*8] correction, pre-scaled 1/8
__device__ float g_Wsum[NB];

// ---------------------------------------------------------------------------
// kA: 8x8 block sums of x -> ll3, one Haar level -> 4 coefficient bands.
// One block per (b,c), 64 threads.
// ---------------------------------------------------------------------------
__global__ void kA(const float* __restrict__ x) {
    int bc = blockIdx.x;              // 0..2047   b = bc>>6, chan = bc&63
    int t = threadIdx.x;              // 0..63
    int i = t >> 3, j = t & 7;
    const float* xp = x + (size_t)bc * NS * NS + (size_t)i * 8 * NS + j * 8;
    float s = 0.f;
#pragma unroll
    for (int r = 0; r < 8; r++) {
        float4 a = *(const float4*)(xp + r * NS);
        float4 b = *(const float4*)(xp + r * NS + 4);
        s += a.x + a.y + a.z + a.w + b.x + b.y + b.z + b.w;
    }
    __shared__ float ll3[64];
    ll3[t] = s * 0.125f;              // 8x8 block sum / 8 == ll3
    __syncthreads();
    if (t < 16) {
        int xy = t;
        int xx = xy >> 2, yy = xy & 3;
        float a = ll3[(2 * xx) * 8 + 2 * yy];
        float b = ll3[(2 * xx) * 8 + 2 * yy + 1];
        float c = ll3[(2 * xx + 1) * 8 + 2 * yy];
        float d = ll3[(2 * xx + 1) * 8 + 2 * yy + 1];
        int bb = bc >> 6, ch = bc & 63;
        float v[4];
        v[0] = (a + b + c + d) * 0.5f; // ll
        v[1] = (a + b - c - d) * 0.5f; // lh
        v[2] = (a - b + c - d) * 0.5f; // hl
        v[3] = (a - b - c + d) * 0.5f; // hh
#pragma unroll
        for (int band = 0; band < 4; band++) {
            g_c [((band * 16 + xy) * 64 + ch) * 32 + bb] = v[band];
            g_c2[((band * 32 + bb) * 16 + xy) * 64 + ch] = v[band];
        }
    }
}

// ---------------------------------------------------------------------------
// kT: transpose weights into [band][e][xy][i][o].
// 384 blocks x 256 threads; each thread handles ONE (i,o) row:
// reads 16 consecutive floats, scatters one per xy (coalesced per xy).
// ---------------------------------------------------------------------------
__global__ void kT(const float* __restrict__ WL, const float* __restrict__ WH) {
    int blk = blockIdx.x;             // 0..383
    int be = blk >> 4;                // band*6+e
    int rr = blk & 15;                // which 256-chunk of io
    int band = be / NE, e = be % NE;
    float* dst = g_Wt + (size_t)be * 16 * 4096;
    const float* src;
    if (band == 0) src = WL + (size_t)e * 65536;
    else           src = WH + (size_t)(e * 3 + (band - 1)) * 65536;

    int io = threadIdx.x + 256 * rr;  // 0..4095
    const float* sp = src + (size_t)io * 16;
    float4 q0 = *(const float4*)(sp);
    float4 q1 = *(const float4*)(sp + 4);
    float4 q2 = *(const float4*)(sp + 8);
    float4 q3 = *(const float4*)(sp + 12);
    float v[16] = {q0.x,q0.y,q0.z,q0.w, q1.x,q1.y,q1.z,q1.w,
                   q2.x,q2.y,q2.z,q2.w, q3.x,q3.y,q3.z,q3.w};
#pragma unroll
    for (int xy = 0; xy < 16; xy++)
        dst[(size_t)xy * 4096 + io] = v[xy];
}

// ---------------------------------------------------------------------------
// kB1: per (band,e,xy): P[b,o] = sum_i c[b,i] * W[i,o].
// 384 blocks x 64 threads; each thread computes a 4b x 8o register tile
// straight from global (L2-resident). No smem.
// ---------------------------------------------------------------------------
__global__ void kB1() {
    int blk = blockIdx.x;             // 0..383
    int xy = blk & 15;
    int e  = (blk >> 4) % NE;
    int band = blk / (16 * NE);
    int t = threadIdx.x;              // 0..63
    int b0 = (t >> 3) * 4;
    int o0 = (t & 7) * 8;

    const float* wp = g_Wt + ((size_t)(band * NE + e) * 16 + xy) * 4096 + o0;
    const float* cp = g_c + ((size_t)(band * 16 + xy) * 64) * 32 + b0;

    float acc[4][8];
#pragma unroll
    for (int bb = 0; bb < 4; bb++)
#pragma unroll
        for (int o = 0; o < 8; o++) acc[bb][o] = 0.f;

#pragma unroll 8
    for (int i = 0; i < 64; i++) {
        float4 c4 = *(const float4*)(cp + i * 32);
        float4 w0 = *(const float4*)(wp + (size_t)i * 64);
        float4 w1 = *(const float4*)(wp + (size_t)i * 64 + 4);
        float cb[4] = {c4.x, c4.y, c4.z, c4.w};
        float wo[8] = {w0.x, w0.y, w0.z, w0.w, w1.x, w1.y, w1.z, w1.w};
#pragma unroll
        for (int bb = 0; bb < 4; bb++)
#pragma unroll
            for (int o = 0; o < 8; o++) acc[bb][o] += cb[bb] * wo[o];
    }

    float* Pp = g_P + ((size_t)(band * NE + e) * 32) * 1024 + xy * 64 + o0;
#pragma unroll
    for (int bb = 0; bb < 4; bb++) {
        float* q = Pp + (size_t)(b0 + bb) * 1024;
        *(float4*)(q)     = make_float4(acc[bb][0], acc[bb][1], acc[bb][2], acc[bb][3]);
        *(float4*)(q + 4) = make_float4(acc[bb][4], acc[bb][5], acc[bb][6], acc[bb][7]);
    }
}

// ---------------------------------------------------------------------------
// kB2: gate-weighted combine over experts, subtract identity, 4x4->8x8 IDWT,
// pre-scale 1/8.  Flat 32768 threads (128 blocks x 256); no smem, no syncs.
// All global reads coalesced (g_c2 layout).
// ---------------------------------------------------------------------------
__global__ void kB2(const float* __restrict__ lam) {
    int g = blockIdx.x * blockDim.x + threadIdx.x;   // 0..32767
    int b = g >> 10, t = g & 1023;
    int xy = t >> 6, o = t & 63;

    const float* lp = lam + b * 8;
    float l0 = __ldg(lp+0), l1 = __ldg(lp+1), l2 = __ldg(lp+2), l3 = __ldg(lp+3);
    float l4 = __ldg(lp+4), l5 = __ldg(lp+5), l6 = __ldg(lp+6), l7 = __ldg(lp+7);
    float w[6] = {l0, l1, l2, l3, l4 + l6, l5 + l7};
    float Wt = l0 + l1 + l2 + l3 + l4 + l5 + l6 + l7;
    if (t == 0) g_Wsum[b] = Wt;

    float Sv[4];
#pragma unroll
    for (int band = 0; band < 4; band++) {
        float s = 0.f;
#pragma unroll
        for (int e = 0; e < NE; e++)
            s += w[e] * g_P[((size_t)(band * NE + e) * 32 + b) * 1024 + t];
        float orig = g_c2[((size_t)(band * 32 + b) * 16 + xy) * 64 + o];
        Sv[band] = s - Wt * orig;
    }
    float x00 = (Sv[0] + Sv[1] + Sv[2] + Sv[3]) * 0.0625f;
    float x01 = (Sv[0] + Sv[1] - Sv[2] - Sv[3]) * 0.0625f;
    float x10 = (Sv[0] - Sv[1] + Sv[2] - Sv[3]) * 0.0625f;
    float x11 = (Sv[0] - Sv[1] - Sv[2] + Sv[3]) * 0.0625f;
    int xx = xy >> 2, yy = xy & 3;
    float* zp = g_z + (size_t)(b * 64 + o) * 64;
    zp[(2 * xx) * 8 + 2 * yy]         = x00;
    zp[(2 * xx) * 8 + 2 * yy + 1]     = x01;
    zp[(2 * xx + 1) * 8 + 2 * yy]     = x10;
    zp[(2 * xx + 1) * 8 + 2 * yy + 1] = x11;
}

// ---------------------------------------------------------------------------
// kC: out = Wsum[b] * x + z[b,c,h/8,w/8].  8 consecutive floats per thread.
// ---------------------------------------------------------------------------
__global__ void kC(const float* __restrict__ x, float* __restrict__ out) {
    int tid = blockIdx.x * blockDim.x + threadIdx.x;  // 0..1048575
    int e0 = tid << 3;
    int b = e0 >> 18;
    int c = (e0 >> 12) & 63;
    int h = (e0 >> 6) & 63;
    int w0 = e0 & 63;
    float W = g_Wsum[b];
    float zv = g_z[(size_t)((b << 6) + c) * 64 + (h >> 3) * 8 + (w0 >> 3)];
    float4 xa = *(const float4*)(x + e0);
    float4 xb = *(const float4*)(x + e0 + 4);
    float4 oa, ob;
    oa.x = fmaf(W, xa.x, zv); oa.y = fmaf(W, xa.y, zv);
    oa.z = fmaf(W, xa.z, zv); oa.w = fmaf(W, xa.w, zv);
    ob.x = fmaf(W, xb.x, zv); ob.y = fmaf(W, xb.y, zv);
    ob.z = fmaf(W, xb.z, zv); ob.w = fmaf(W, xb.w, zv);
    *(float4*)(out + e0)     = oa;
    *(float4*)(out + e0 + 4) = ob;
}

// ---------------------------------------------------------------------------
extern "C" void kernel_launch(void* const* d_in, const int* in_sizes, int n_in,
                              void* d_out, int out_size) {
    const float* x   = (const float*)d_in[0];  // [32,64,64,64]
    const float* lam = (const float*)d_in[1];  // [32,1,8,1]
    const float* WL  = (const float*)d_in[2];  // [8,64,64,4,4]
    const float* WH  = (const float*)d_in[3];  // [8,3,64,64,4,4]
    float* out = (float*)d_out;

    kT<<<4 * NE * 16, 256>>>(WL, WH);
    kA<<<NB * NC, 64>>>(x);
    kB1<<<4 * NE * 16, 64>>>();
    kB2<<<128, 256>>>(lam);
    kC<<<(NB * NC * NS * NS / 8 + 255) / 256, 256>>>(x, out);
    (void)in_sizes; (void)n_in; (void)out_size;
}